// round 15
// baseline (speedup 1.0000x reference)
#include <cuda_runtime.h>
#include <math.h>

#define Qn 2048
#define Dn 256
#define Nn 32768
#define Hn 8
#define STn 64
#define DINn 512
#define CONVn 640
#define NPROJn 1160
#define HIDn 1024
#define KCn 4
#define Ln 2048

// ---------------- scratch (device globals) ----------------
__device__ float g_q[Qn*Dn];
__device__ float g_fbar[Qn*Dn];
__device__ float g_vbar[Qn*Dn];
__device__ float g_wtmp[Qn*Dn];
__device__ float g_wo[Qn*Dn];
__device__ float g_x[Qn*Dn];
__device__ float g_xn[Qn*Dn];
__device__ float g_xs[2*Qn*Dn];
__device__ float g_proj[2*Qn*NPROJn];
__device__ float g_xbc[2*Qn*CONVn];
__device__ float g_dt[2*Qn*Hn];
__device__ float g_dAr[2*Qn*Hn];
__device__ float g_ys[2*Qn*DINn];
__device__ float g_gated[2*Qn*DINn];
__device__ float g_mo[2*Qn*Dn];
__device__ float g_ffnh[Qn*HIDn];
__device__ float g_ffno[Qn*Dn];
__device__ float g_part[4*Qn*Dn*2];   // split-K partials (max 2 slices x 4096 x 256)
__device__ float4 g_sp4[Nn];
__device__ int g_idx[Qn*8];
__device__ int g_inv[2*Qn];

// ---------------- helpers ----------------
template<int NT>
__device__ __forceinline__ float blockSum(float v) {
    __shared__ float sm[NT/32];
    unsigned m = 0xffffffffu;
    v += __shfl_xor_sync(m, v, 16);
    v += __shfl_xor_sync(m, v, 8);
    v += __shfl_xor_sync(m, v, 4);
    v += __shfl_xor_sync(m, v, 2);
    v += __shfl_xor_sync(m, v, 1);
    int w = threadIdx.x >> 5;
    if ((threadIdx.x & 31) == 0) sm[w] = v;
    __syncthreads();
    float t = sm[0];
#pragma unroll
    for (int k = 1; k < NT/32; k++) t += sm[k];
    __syncthreads();
    return t;
}

// ============ big GEMM: 128x128 tile, BK=8, 8x8 microtile, double-buffered ============
// C[M,N] = A[M,K] @ W[N,K]^T ; optional split-K via gridDim.z (Ksub per slice).
// gridDim.z == 1: applies bias/act and writes C directly.
// gridDim.z  > 1: raw partial per slice at C + z*M*N (reduce kernel finishes).
// Requires M%128==0, Ksub%8==0, N%8==0, rows 16B-aligned (K%4==0).
__global__ __launch_bounds__(256) void gemm_big(
    const float* __restrict__ A, const float* __restrict__ W,
    const float* __restrict__ bias, float* __restrict__ C,
    int M, int N, int K, int act, int Ksub)
{
    __shared__ float As[2][8][128];
    __shared__ float Ws[2][8][128];
    int tid = threadIdx.x;
    int m0 = blockIdx.y * 128;
    int n0 = blockIdx.x * 128;
    int ks = blockIdx.z * Ksub;

    const float* Ab = A + (size_t)m0 * K + ks;
    const float* Wb = W + ks;
    float* Cb = C + (size_t)blockIdx.z * M * N;

    int lrow = tid >> 1;           // 0..127
    int lcol = (tid & 1) * 4;      // 0 or 4
    bool wok = (n0 + lrow) < N;

    float4 ar4 = *(const float4*)&Ab[(size_t)lrow * K + lcol];
    float4 wr4 = wok ? *(const float4*)&Wb[(size_t)(n0 + lrow) * K + lcol]
                     : make_float4(0.f, 0.f, 0.f, 0.f);
    As[0][lcol+0][lrow] = ar4.x; As[0][lcol+1][lrow] = ar4.y;
    As[0][lcol+2][lrow] = ar4.z; As[0][lcol+3][lrow] = ar4.w;
    Ws[0][lcol+0][lrow] = wr4.x; Ws[0][lcol+1][lrow] = wr4.y;
    Ws[0][lcol+2][lrow] = wr4.z; Ws[0][lcol+3][lrow] = wr4.w;
    __syncthreads();

    int tx = tid & 15, ty = tid >> 4;
    float acc[8][8];
#pragma unroll
    for (int i = 0; i < 8; i++)
#pragma unroll
        for (int j = 0; j < 8; j++) acc[i][j] = 0.f;

    int buf = 0;
    for (int k0 = 0; k0 < Ksub; k0 += 8) {
        bool more = (k0 + 8) < Ksub;
        if (more) {
            ar4 = *(const float4*)&Ab[(size_t)lrow * K + k0 + 8 + lcol];
            wr4 = wok ? *(const float4*)&Wb[(size_t)(n0 + lrow) * K + k0 + 8 + lcol]
                      : make_float4(0.f, 0.f, 0.f, 0.f);
        }
#pragma unroll
        for (int k = 0; k < 8; k++) {
            float4 a0 = *(const float4*)&As[buf][k][ty * 8];
            float4 a1 = *(const float4*)&As[buf][k][ty * 8 + 4];
            float4 b0 = *(const float4*)&Ws[buf][k][tx * 8];
            float4 b1 = *(const float4*)&Ws[buf][k][tx * 8 + 4];
            float ar[8] = {a0.x, a0.y, a0.z, a0.w, a1.x, a1.y, a1.z, a1.w};
            float br[8] = {b0.x, b0.y, b0.z, b0.w, b1.x, b1.y, b1.z, b1.w};
#pragma unroll
            for (int i = 0; i < 8; i++)
#pragma unroll
                for (int j = 0; j < 8; j++)
                    acc[i][j] = fmaf(ar[i], br[j], acc[i][j]);
        }
        if (more) {
            int nb = buf ^ 1;
            As[nb][lcol+0][lrow] = ar4.x; As[nb][lcol+1][lrow] = ar4.y;
            As[nb][lcol+2][lrow] = ar4.z; As[nb][lcol+3][lrow] = ar4.w;
            Ws[nb][lcol+0][lrow] = wr4.x; Ws[nb][lcol+1][lrow] = wr4.y;
            Ws[nb][lcol+2][lrow] = wr4.z; Ws[nb][lcol+3][lrow] = wr4.w;
        }
        __syncthreads();
        buf ^= 1;
    }

    int ncol = n0 + tx * 8;
    bool nok = ncol < N;   // N%8==0 -> all 8 valid when true
    if (gridDim.z == 1) {
        float bj[8];
#pragma unroll
        for (int j = 0; j < 8; j++) bj[j] = (bias && nok) ? bias[ncol + j] : 0.f;
#pragma unroll
        for (int i = 0; i < 8; i++) {
            if (!nok) break;
            int mrow = m0 + ty * 8 + i;
            float v[8];
#pragma unroll
            for (int j = 0; j < 8; j++) {
                float t = acc[i][j] + bj[j];
                if (act == 1) t = 0.5f * t * (1.f + erff(t * 0.7071067811865475f));
                v[j] = t;
            }
            *(float4*)&Cb[(size_t)mrow * N + ncol] = make_float4(v[0], v[1], v[2], v[3]);
            *(float4*)&Cb[(size_t)mrow * N + ncol + 4] = make_float4(v[4], v[5], v[6], v[7]);
        }
    } else {
#pragma unroll
        for (int i = 0; i < 8; i++) {
            if (!nok) break;
            int mrow = m0 + ty * 8 + i;
            *(float4*)&Cb[(size_t)mrow * N + ncol] =
                make_float4(acc[i][0], acc[i][1], acc[i][2], acc[i][3]);
            *(float4*)&Cb[(size_t)mrow * N + ncol + 4] =
                make_float4(acc[i][4], acc[i][5], acc[i][6], acc[i][7]);
        }
    }
}

// split-K reduce: C[i] = act(sum_s P[s][i] + bias[i % N])
__global__ void reduce_splitk(const float* __restrict__ P, const float* __restrict__ bias,
                              float* __restrict__ C, int MN, int N, int S, int act)
{
    int i = blockIdx.x * blockDim.x + threadIdx.x;
    if (i < MN) {
        float v = 0.f;
        for (int s = 0; s < S; s++) v += P[(size_t)s * MN + i];
        if (bias) v += bias[i % N];
        if (act == 1) v = 0.5f * v * (1.f + erff(v * 0.7071067811865475f));
        C[i] = v;
    }
}

// ---------------- small GEMM (64x64, used for attn projections) ----------------
__global__ __launch_bounds__(256) void gemm_kernel(
    const float* __restrict__ A, const float* __restrict__ W,
    const float* __restrict__ bias, float* __restrict__ C,
    int M, int N, int K, int act)
{
    __shared__ float As[16][68];
    __shared__ float Ws[16][68];
    int tx = threadIdx.x, ty = threadIdx.y;
    int tid = ty * 16 + tx;
    int m0 = blockIdx.y * 64;
    int n0 = blockIdx.x * 64;
    int lr = tid >> 2;
    int lc = (tid & 3) * 4;

    float acc[4][4];
#pragma unroll
    for (int i = 0; i < 4; i++)
#pragma unroll
        for (int j = 0; j < 4; j++) acc[i][j] = 0.f;

    for (int k0 = 0; k0 < K; k0 += 16) {
        float4 av = *(const float4*)&A[(size_t)(m0 + lr) * K + k0 + lc];
        As[lc+0][lr] = av.x; As[lc+1][lr] = av.y; As[lc+2][lr] = av.z; As[lc+3][lr] = av.w;
        int wr = n0 + lr;
        float4 wv = make_float4(0.f, 0.f, 0.f, 0.f);
        if (wr < N) wv = *(const float4*)&W[(size_t)wr * K + k0 + lc];
        Ws[lc+0][lr] = wv.x; Ws[lc+1][lr] = wv.y; Ws[lc+2][lr] = wv.z; Ws[lc+3][lr] = wv.w;
        __syncthreads();
#pragma unroll
        for (int k = 0; k < 16; k++) {
            float4 a4 = *(const float4*)&As[k][ty * 4];
            float4 b4 = *(const float4*)&Ws[k][tx * 4];
            float ar[4] = {a4.x, a4.y, a4.z, a4.w};
            float br[4] = {b4.x, b4.y, b4.z, b4.w};
#pragma unroll
            for (int i = 0; i < 4; i++)
#pragma unroll
                for (int j = 0; j < 4; j++)
                    acc[i][j] += ar[i] * br[j];
        }
        __syncthreads();
    }
#pragma unroll
    for (int i = 0; i < 4; i++) {
        int mrow = m0 + ty * 4 + i;
#pragma unroll
        for (int j = 0; j < 4; j++) {
            int ncol = n0 + tx * 4 + j;
            if (ncol < N) {
                float v = acc[i][j];
                if (bias) v += bias[ncol];
                if (act == 1) v = 0.5f * v * (1.f + erff(v * 0.7071067811865475f));
                C[(size_t)mrow * N + ncol] = v;
            }
        }
    }
}

// ---------------- pack sp coords ----------------
__global__ void pack_sp_kernel(const float* __restrict__ sp) {
    int i = blockIdx.x * blockDim.x + threadIdx.x;
    if (i < Nn) {
        float x = sp[3*i], y = sp[3*i+1], z = sp[3*i+2];
        g_sp4[i] = make_float4(x, y, z, x*x + y*y + z*z);
    }
}

// ---------------- KNN ----------------
__device__ __forceinline__ bool knn_less(float da, int ia, float db, int ib) {
    return (da < db) || (da == db && ia < ib);
}

__global__ __launch_bounds__(256) void knn_kernel(const float* __restrict__ qpos) {
    __shared__ float4 tile[2048];
    int tid = threadIdx.x;
    int ql = tid & 15;
    int lg = tid >> 4;
    int q = blockIdx.x * 16 + ql;
    float qx = qpos[3*q], qy = qpos[3*q+1], qz = qpos[3*q+2];

    float bd[8]; int bi[8];
#pragma unroll
    for (int j = 0; j < 8; j++) { bd[j] = 3.4e38f; bi[j] = 0x7fffffff; }

    for (int tb = 0; tb < Nn; tb += 2048) {
        __syncthreads();
        for (int i = tid; i < 2048; i += 256) tile[i] = g_sp4[tb + i];
        __syncthreads();
        for (int i = lg; i < 2048; i += 16) {
            float4 s = tile[i];
            float d = s.w - 2.f * (qx*s.x + qy*s.y + qz*s.z);
            int n = tb + i;
            if (knn_less(d, n, bd[7], bi[7])) {
                float cd = d; int ci = n;
#pragma unroll
                for (int p = 0; p < 8; p++) {
                    if (knn_less(cd, ci, bd[p], bi[p])) {
                        float tf = bd[p]; bd[p] = cd; cd = tf;
                        int ti = bi[p]; bi[p] = ci; ci = ti;
                    }
                }
            }
        }
    }
    __syncthreads();
    float* sd = (float*)tile;
    int* si = (int*)(sd + 2048);
#pragma unroll
    for (int j = 0; j < 8; j++) { sd[tid*8+j] = bd[j]; si[tid*8+j] = bi[j]; }
    __syncthreads();
    for (int st = 8; st >= 1; st >>= 1) {
        if (lg < st) {
            int op = tid + st * 16;
#pragma unroll
            for (int j = 0; j < 8; j++) {
                float cd = sd[op*8+j]; int ci = si[op*8+j];
                if (knn_less(cd, ci, bd[7], bi[7])) {
#pragma unroll
                    for (int p = 0; p < 8; p++) {
                        if (knn_less(cd, ci, bd[p], bi[p])) {
                            float tf = bd[p]; bd[p] = cd; cd = tf;
                            int ti = bi[p]; bi[p] = ci; ci = ti;
                        }
                    }
                }
            }
#pragma unroll
            for (int j = 0; j < 8; j++) { sd[tid*8+j] = bd[j]; si[tid*8+j] = bi[j]; }
        }
        __syncthreads();
    }
    if (lg == 0) {
#pragma unroll
        for (int j = 0; j < 8; j++) g_idx[q*8+j] = bi[j];
    }
}

// ---------------- kw softmax + weighted feature mix ----------------
__global__ __launch_bounds__(256) void kwfbar_kernel(
    const float* __restrict__ wk, const float* __restrict__ wb,
    const float* __restrict__ feats)
{
    int q = blockIdx.x;
    __shared__ float sc[8];
    int w = threadIdx.x >> 5, lane = threadIdx.x & 31;
    const float* qr = g_q + (size_t)q * Dn;
    float s = 0.f;
    for (int d = lane; d < Dn; d += 32) s += qr[d] * wk[w*Dn + d];
    unsigned m = 0xffffffffu;
    s += __shfl_xor_sync(m, s, 16); s += __shfl_xor_sync(m, s, 8);
    s += __shfl_xor_sync(m, s, 4);  s += __shfl_xor_sync(m, s, 2);
    s += __shfl_xor_sync(m, s, 1);
    if (lane == 0) sc[w] = s + wb[w];
    __syncthreads();
    float mx = sc[0];
#pragma unroll
    for (int k = 1; k < 8; k++) mx = fmaxf(mx, sc[k]);
    float kwv[8]; float ssum = 0.f;
#pragma unroll
    for (int k = 0; k < 8; k++) { kwv[k] = expf(sc[k] - mx); ssum += kwv[k]; }
    float inv = 1.f / ssum;
    int d = threadIdx.x;
    float acc = 0.f;
#pragma unroll
    for (int k = 0; k < 8; k++) {
        int id = g_idx[q*8 + k];
        acc += kwv[k] * inv * feats[(size_t)id * Dn + d];
    }
    g_fbar[(size_t)q * Dn + d] = acc;
}

__global__ void mul_kernel() {
    int i = blockIdx.x * blockDim.x + threadIdx.x;
    if (i < Qn*Dn) g_wtmp[i] = g_q[i] * g_vbar[i];
}

// ---------------- LayerNorm: dst = LN(a [+ b]) ----------------
__global__ __launch_bounds__(256) void ln_kernel(
    float* __restrict__ dst, const float* __restrict__ a, const float* __restrict__ b)
{
    int row = blockIdx.x, d = threadIdx.x;
    float v = a[(size_t)row*Dn + d];
    if (b) v += b[(size_t)row*Dn + d];
    float mean = blockSum<256>(v) * (1.f/Dn);
    float c = v - mean;
    float var = blockSum<256>(c*c) * (1.f/Dn);
    dst[(size_t)row*Dn + d] = c * rsqrtf(var + 1e-5f);
}

__global__ void gather_kernel(const int* __restrict__ order) {
    int r = blockIdx.x;
    int src = order[r];
    g_xs[(size_t)r*Dn + threadIdx.x] = g_xn[(size_t)src*Dn + threadIdx.x];
}

__global__ void inv_kernel(const int* __restrict__ order) {
    int i = blockIdx.x * blockDim.x + threadIdx.x;
    if (i < 2*Qn) {
        int p = i >> 11, j = i & 2047;
        g_inv[p*Qn + order[i]] = j;
    }
}

// ---------------- causal depthwise conv(4) + silu ----------------
__global__ void conv_kernel(const float* __restrict__ Wc, const float* __restrict__ bc) {
    int t = blockIdx.x, b = blockIdx.y, c = threadIdx.x;
    size_t rbase = (size_t)(b*Ln + t) * NPROJn + 512 + c;
    float acc = bc[c];
#pragma unroll
    for (int j = 0; j < 4; j++) {
        int tt = t + j - 3;
        if (tt >= 0) acc += g_proj[rbase + (size_t)(tt - t) * NPROJn] * Wc[c*4 + j];
    }
    float sg = 1.f / (1.f + expf(-acc));
    g_xbc[(size_t)(b*Ln + t) * CONVn + c] = acc * sg;
}

__global__ void dt_kernel(const float* __restrict__ dtb, const float* __restrict__ Alog) {
    int i = blockIdx.x * blockDim.x + threadIdx.x;
    if (i < 2*Ln*Hn) {
        int h = i & 7, row = i >> 3;
        float x = g_proj[(size_t)row*NPROJn + 1152 + h] + dtb[h];
        float dt = (x > 20.f) ? x : log1pf(expf(x));
        float A = -expf(Alog[h]);
        g_dt[i] = dt;
        g_dAr[i] = expf(dt * A);
    }
}

// ---------------- recurrent SSM scan ----------------
// grid 128 = b(2) x h(8) x dchunk(8), block 128 = dlocal(8) x sgroup(16, 4 s each)
__global__ __launch_bounds__(128) void scan_kernel() {
    int bx = blockIdx.x;
    int b = bx >> 6;
    int h = (bx >> 3) & 7;
    int dch = bx & 7;
    int tid = threadIdx.x;
    int dl = tid >> 4;
    int s0 = (tid & 15) * 4;
    int dg = dch * 8 + dl;

    __shared__ float sacc[16][132];

    const float* xbcb = g_xbc + (size_t)b * Ln * CONVn;
    const float* dAb = g_dAr + (size_t)b * Ln * Hn + h;
    const float* dtbp = g_dt + (size_t)b * Ln * Hn + h;

    float h0 = 0.f, h1 = 0.f, h2 = 0.f, h3 = 0.f;

    float4 Bp = *(const float4*)(xbcb + 512 + s0);
    float4 Cp = *(const float4*)(xbcb + 576 + s0);
    float xp = xbcb[h*64 + dg];
    float dAp = dAb[0], dtp = dtbp[0];

    for (int tile = 0; tile < Ln/16; ++tile) {
#pragma unroll
        for (int tt = 0; tt < 16; ++tt) {
            int t = tile * 16 + tt;
            float4 Bv = Bp; float4 Cv = Cp;
            float xv = xp, dA = dAp, dt = dtp;
            if (t + 1 < Ln) {
                const float* r = xbcb + (size_t)(t + 1) * CONVn;
                Bp = *(const float4*)(r + 512 + s0);
                Cp = *(const float4*)(r + 576 + s0);
                xp = r[h*64 + dg];
                dAp = dAb[(size_t)(t + 1) * Hn];
                dtp = dtbp[(size_t)(t + 1) * Hn];
            }
            float dtx = dt * xv;
            h0 = h0 * dA + dtx * Bv.x;
            h1 = h1 * dA + dtx * Bv.y;
            h2 = h2 * dA + dtx * Bv.z;
            h3 = h3 * dA + dtx * Bv.w;
            sacc[tt][tid] = h0*Cv.x + h1*Cv.y + h2*Cv.z + h3*Cv.w;
        }
        __syncthreads();
        int tt = tid >> 3, dd = tid & 7;
        float y = 0.f;
#pragma unroll
        for (int j = 0; j < 16; j++) y += sacc[tt][dd*16 + j];
        int t = tile * 16 + tt;
        g_ys[(size_t)(b*Ln + t) * DINn + h*64 + dch*8 + dd] = y;
        __syncthreads();
    }
}

// ---------------- y + D*x, silu(z) gate, gated RMSNorm ----------------
__global__ __launch_bounds__(128) void gated_kernel(
    const float* __restrict__ Dl, const float* __restrict__ rmsw)
{
    int row = blockIdx.x, tid = threadIdx.x;
    float gv[4]; float ss = 0.f;
#pragma unroll
    for (int e = 0; e < 4; e++) {
        int c = e * 128 + tid;
        int h = c >> 6;
        float ys = g_ys[(size_t)row*DINn + c];
        float xh = g_xbc[(size_t)row*CONVn + c];
        float z = g_proj[(size_t)row*NPROJn + c];
        float u = ys + Dl[h] * xh;
        float g = u * (z / (1.f + expf(-z)));
        gv[e] = g;
        ss += g * g;
    }
    float tot = blockSum<128>(ss);
    float r = rsqrtf(tot * (1.f/DINn) + 1e-5f);
#pragma unroll
    for (int e = 0; e < 4; e++) {
        int c = e * 128 + tid;
        g_gated[(size_t)row*DINn + c] = gv[e] * r * rmsw[c];
    }
}

// ---------------- unsort + mean + residual + LN (updates g_x) ----------------
__global__ __launch_bounds__(256) void combine_kernel() {
    int i = blockIdx.x, d = threadIdx.x;
    int i0 = g_inv[i];
    int i1 = g_inv[Qn + i];
    float v = g_x[(size_t)i*Dn + d]
            + 0.5f * (g_mo[(size_t)i0*Dn + d] + g_mo[(size_t)(Qn + i1)*Dn + d]);
    float mean = blockSum<256>(v) * (1.f/Dn);
    float c = v - mean;
    float var = blockSum<256>(c*c) * (1.f/Dn);
    g_x[(size_t)i*Dn + d] = c * rsqrtf(var + 1e-5f);
}

// ---------------- host ----------------
extern "C" void kernel_launch(void* const* d_in, const int* in_sizes, int n_in,
                              void* d_out, int out_size) {
    const float* query  = (const float*)d_in[0];
    const float* qpos   = (const float*)d_in[1];
    const float* feats  = (const float*)d_in[2];
    const float* spc    = (const float*)d_in[3];
    const float* w_q    = (const float*)d_in[4];
    const float* w_v    = (const float*)d_in[5];
    const float* w_o    = (const float*)d_in[6];
    const float* w_k    = (const float*)d_in[7];
    const float* w_b    = (const float*)d_in[8];
    const float* Win    = (const float*)d_in[9];
    const float* Wconv  = (const float*)d_in[10];
    const float* bconv  = (const float*)d_in[11];
    const float* Alog   = (const float*)d_in[12];
    const float* Dh     = (const float*)d_in[13];
    const float* dtbias = (const float*)d_in[14];
    const float* rmsw   = (const float*)d_in[15];
    const float* Wout   = (const float*)d_in[16];
    const float* fw1    = (const float*)d_in[17];
    const float* fb1    = (const float*)d_in[18];
    const float* fw2    = (const float*)d_in[19];
    const float* fb2    = (const float*)d_in[20];
    const int*   order  = (const int*)d_in[21];
    float* out = (float*)d_out;

    void *vq, *vfbar, *vvbar, *vwtmp, *vwo, *vx, *vxn, *vxs, *vproj, *vgated, *vmo,
         *vffnh, *vffno, *vpart;
    cudaGetSymbolAddress(&vq, g_q);
    cudaGetSymbolAddress(&vfbar, g_fbar);
    cudaGetSymbolAddress(&vvbar, g_vbar);
    cudaGetSymbolAddress(&vwtmp, g_wtmp);
    cudaGetSymbolAddress(&vwo, g_wo);
    cudaGetSymbolAddress(&vx, g_x);
    cudaGetSymbolAddress(&vxn, g_xn);
    cudaGetSymbolAddress(&vxs, g_xs);
    cudaGetSymbolAddress(&vproj, g_proj);
    cudaGetSymbolAddress(&vgated, g_gated);
    cudaGetSymbolAddress(&vmo, g_mo);
    cudaGetSymbolAddress(&vffnh, g_ffnh);
    cudaGetSymbolAddress(&vffno, g_ffno);
    cudaGetSymbolAddress(&vpart, g_part);
    float* p_q = (float*)vq;       float* p_fbar = (float*)vfbar;
    float* p_vbar = (float*)vvbar; float* p_wtmp = (float*)vwtmp;
    float* p_wo = (float*)vwo;     float* p_x = (float*)vx;
    float* p_xn = (float*)vxn;     float* p_xs = (float*)vxs;
    float* p_proj = (float*)vproj; float* p_gated = (float*)vgated;
    float* p_mo = (float*)vmo;     float* p_ffnh = (float*)vffnh;
    float* p_ffno = (float*)vffno; float* p_part = (float*)vpart;

    dim3 gb(16, 16);

    // --- stage 1: KNN + aggregation ---
    pack_sp_kernel<<<Nn/256, 256>>>(spc);
    knn_kernel<<<Qn/16, 256>>>(qpos);
    gemm_kernel<<<dim3(Dn/64, Qn/64), gb>>>(query, w_q, nullptr, p_q, Qn, Dn, Dn, 0);
    kwfbar_kernel<<<Qn, 256>>>(w_k, w_b, feats);
    gemm_kernel<<<dim3(Dn/64, Qn/64), gb>>>(p_fbar, w_v, nullptr, p_vbar, Qn, Dn, Dn, 0);
    mul_kernel<<<(Qn*Dn)/256, 256>>>();
    gemm_kernel<<<dim3(Dn/64, Qn/64), gb>>>(p_wtmp, w_o, nullptr, p_wo, Qn, Dn, Dn, 0);
    ln_kernel<<<Qn, 256>>>(p_x, p_wo, query);

    inv_kernel<<<(2*Qn)/256, 256>>>(order);

    // --- stage 2: two Mamba2 SSM layers ---
    for (int l = 0; l < 2; l++) {
        const float* Win_l   = Win   + (size_t)l * NPROJn * Dn;
        const float* Wconv_l = Wconv + (size_t)l * CONVn * KCn;
        const float* bconv_l = bconv + (size_t)l * CONVn;
        const float* Alog_l  = Alog  + l * Hn;
        const float* D_l     = Dh    + l * Hn;
        const float* dtb_l   = dtbias+ l * Hn;
        const float* rmsw_l  = rmsw  + l * DINn;
        const float* Wout_l  = Wout  + (size_t)l * Dn * DINn;

        ln_kernel<<<Qn, 256>>>(p_xn, p_x, nullptr);
        gather_kernel<<<2*Qn, 256>>>(order);
        // proj = xs @ Win^T : [4096,1160,256]
        gemm_big<<<dim3((NPROJn + 127)/128, (2*Qn)/128, 1), 256>>>(
            p_xs, Win_l, nullptr, p_proj, 2*Qn, NPROJn, Dn, 0, Dn);
        conv_kernel<<<dim3(Ln, 2), CONVn>>>(Wconv_l, bconv_l);
        dt_kernel<<<(2*Ln*Hn)/256, 256>>>(dtb_l, Alog_l);
        scan_kernel<<<128, 128>>>();
        gated_kernel<<<2*Qn, 128>>>(D_l, rmsw_l);
        // mo = gated @ Wout^T : [4096,256,512] split-K=2
        gemm_big<<<dim3(Dn/128, (2*Qn)/128, 2), 256>>>(
            p_gated, Wout_l, nullptr, p_part, 2*Qn, Dn, DINn, 0, DINn/2);
        reduce_splitk<<<(2*Qn*Dn)/256, 256>>>(p_part, nullptr, p_mo, 2*Qn*Dn, Dn, 2, 0);
        combine_kernel<<<Qn, 256>>>();
    }

    // --- stage 3: FFN ---
    gemm_big<<<dim3(HIDn/128, Qn/128, 1), 256>>>(p_x, fw1, fb1, p_ffnh, Qn, HIDn, Dn, 1, Dn);
    // ffn2: [2048,256,1024] split-K=4
    gemm_big<<<dim3(Dn/128, Qn/128, 4), 256>>>(
        p_ffnh, fw2, nullptr, p_part, Qn, Dn, HIDn, 0, HIDn/4);
    reduce_splitk<<<(Qn*Dn)/256, 256>>>(p_part, fb2, p_ffno, Qn*Dn, Dn, 4, 0);
    ln_kernel<<<Qn, 256>>>(out, p_ffno, p_x);
}

// round 16
// speedup vs baseline: 1.7508x; 1.7508x over previous
#include <cuda_runtime.h>
#include <math.h>

#define Qn 2048
#define Dn 256
#define Nn 32768
#define Hn 8
#define STn 64
#define DINn 512
#define CONVn 640
#define NPROJn 1160
#define HIDn 1024
#define KCn 4
#define Ln 2048

// ---------------- scratch (device globals) ----------------
__device__ float g_q[Qn*Dn];
__device__ float g_fbar[Qn*Dn];
__device__ float g_vbar[Qn*Dn];
__device__ float g_wtmp[Qn*Dn];
__device__ float g_wo[Qn*Dn];
__device__ float g_x[Qn*Dn];
__device__ float g_xn[Qn*Dn];
__device__ float g_xs[2*Qn*Dn];
__device__ float g_proj[2*Qn*NPROJn];
__device__ float g_xbc[2*Qn*CONVn];
__device__ float g_dt[2*Qn*Hn];
__device__ float g_dAr[2*Qn*Hn];
__device__ float g_ys[2*Qn*DINn];
__device__ float g_gated[2*Qn*DINn];
__device__ float g_mo[2*Qn*Dn];
__device__ float g_ffnh[Qn*HIDn];
__device__ float g_ffno[Qn*Dn];
__device__ float4 g_sp4[Nn];
__device__ int g_idx[Qn*8];
__device__ int g_inv[2*Qn];

// ---------------- helpers ----------------
template<int NT>
__device__ __forceinline__ float blockSum(float v) {
    __shared__ float sm[NT/32];
    unsigned m = 0xffffffffu;
    v += __shfl_xor_sync(m, v, 16);
    v += __shfl_xor_sync(m, v, 8);
    v += __shfl_xor_sync(m, v, 4);
    v += __shfl_xor_sync(m, v, 2);
    v += __shfl_xor_sync(m, v, 1);
    int w = threadIdx.x >> 5;
    if ((threadIdx.x & 31) == 0) sm[w] = v;
    __syncthreads();
    float t = sm[0];
#pragma unroll
    for (int k = 1; k < NT/32; k++) t += sm[k];
    __syncthreads();
    return t;
}

// ---------------- GEMM: C = act(A[M,K] @ W[N,K]^T + bias) ----------------
// BM=BN=64, BK=16, 256 threads, 4x4 microtile. M%64==0, K%16==0 guaranteed.
__global__ __launch_bounds__(256) void gemm_kernel(
    const float* __restrict__ A, const float* __restrict__ W,
    const float* __restrict__ bias, float* __restrict__ C,
    int M, int N, int K, int act)
{
    __shared__ float As[16][68];
    __shared__ float Ws[16][68];
    int tx = threadIdx.x, ty = threadIdx.y;
    int tid = ty * 16 + tx;
    int m0 = blockIdx.y * 64;
    int n0 = blockIdx.x * 64;
    int lr = tid >> 2;
    int lc = (tid & 3) * 4;

    float acc[4][4];
#pragma unroll
    for (int i = 0; i < 4; i++)
#pragma unroll
        for (int j = 0; j < 4; j++) acc[i][j] = 0.f;

    for (int k0 = 0; k0 < K; k0 += 16) {
        float4 av = *(const float4*)&A[(size_t)(m0 + lr) * K + k0 + lc];
        As[lc+0][lr] = av.x; As[lc+1][lr] = av.y; As[lc+2][lr] = av.z; As[lc+3][lr] = av.w;
        int wr = n0 + lr;
        float4 wv = make_float4(0.f, 0.f, 0.f, 0.f);
        if (wr < N) wv = *(const float4*)&W[(size_t)wr * K + k0 + lc];
        Ws[lc+0][lr] = wv.x; Ws[lc+1][lr] = wv.y; Ws[lc+2][lr] = wv.z; Ws[lc+3][lr] = wv.w;
        __syncthreads();
#pragma unroll
        for (int k = 0; k < 16; k++) {
            float4 a4 = *(const float4*)&As[k][ty * 4];
            float4 b4 = *(const float4*)&Ws[k][tx * 4];
            float ar[4] = {a4.x, a4.y, a4.z, a4.w};
            float br[4] = {b4.x, b4.y, b4.z, b4.w};
#pragma unroll
            for (int i = 0; i < 4; i++)
#pragma unroll
                for (int j = 0; j < 4; j++)
                    acc[i][j] += ar[i] * br[j];
        }
        __syncthreads();
    }
#pragma unroll
    for (int i = 0; i < 4; i++) {
        int mrow = m0 + ty * 4 + i;
#pragma unroll
        for (int j = 0; j < 4; j++) {
            int ncol = n0 + tx * 4 + j;
            if (ncol < N) {
                float v = acc[i][j];
                if (bias) v += bias[ncol];
                if (act == 1) v = 0.5f * v * (1.f + erff(v * 0.7071067811865475f));
                C[(size_t)mrow * N + ncol] = v;
            }
        }
    }
}

// ---------------- pack sp coords ----------------
__global__ void pack_sp_kernel(const float* __restrict__ sp) {
    int i = blockIdx.x * blockDim.x + threadIdx.x;
    if (i < Nn) {
        float x = sp[3*i], y = sp[3*i+1], z = sp[3*i+2];
        g_sp4[i] = make_float4(x, y, z, x*x + y*y + z*z);
    }
}

// ---------------- KNN ----------------
__device__ __forceinline__ bool knn_less(float da, int ia, float db, int ib) {
    return (da < db) || (da == db && ia < ib);
}

__global__ __launch_bounds__(256) void knn_kernel(const float* __restrict__ qpos) {
    __shared__ float4 tile[2048];
    int tid = threadIdx.x;
    int ql = tid & 15;
    int lg = tid >> 4;
    int q = blockIdx.x * 16 + ql;
    float qx = qpos[3*q], qy = qpos[3*q+1], qz = qpos[3*q+2];

    float bd[8]; int bi[8];
#pragma unroll
    for (int j = 0; j < 8; j++) { bd[j] = 3.4e38f; bi[j] = 0x7fffffff; }

    for (int tb = 0; tb < Nn; tb += 2048) {
        __syncthreads();
        for (int i = tid; i < 2048; i += 256) tile[i] = g_sp4[tb + i];
        __syncthreads();
        for (int i = lg; i < 2048; i += 16) {
            float4 s = tile[i];
            float d = s.w - 2.f * (qx*s.x + qy*s.y + qz*s.z);
            int n = tb + i;
            if (knn_less(d, n, bd[7], bi[7])) {
                float cd = d; int ci = n;
#pragma unroll
                for (int p = 0; p < 8; p++) {
                    if (knn_less(cd, ci, bd[p], bi[p])) {
                        float tf = bd[p]; bd[p] = cd; cd = tf;
                        int ti = bi[p]; bi[p] = ci; ci = ti;
                    }
                }
            }
        }
    }
    __syncthreads();
    float* sd = (float*)tile;
    int* si = (int*)(sd + 2048);
#pragma unroll
    for (int j = 0; j < 8; j++) { sd[tid*8+j] = bd[j]; si[tid*8+j] = bi[j]; }
    __syncthreads();
    for (int st = 8; st >= 1; st >>= 1) {
        if (lg < st) {
            int op = tid + st * 16;
#pragma unroll
            for (int j = 0; j < 8; j++) {
                float cd = sd[op*8+j]; int ci = si[op*8+j];
                if (knn_less(cd, ci, bd[7], bi[7])) {
#pragma unroll
                    for (int p = 0; p < 8; p++) {
                        if (knn_less(cd, ci, bd[p], bi[p])) {
                            float tf = bd[p]; bd[p] = cd; cd = tf;
                            int ti = bi[p]; bi[p] = ci; ci = ti;
                        }
                    }
                }
            }
#pragma unroll
            for (int j = 0; j < 8; j++) { sd[tid*8+j] = bd[j]; si[tid*8+j] = bi[j]; }
        }
        __syncthreads();
    }
    if (lg == 0) {
#pragma unroll
        for (int j = 0; j < 8; j++) g_idx[q*8+j] = bi[j];
    }
}

// ---------------- kw softmax + weighted feature mix ----------------
__global__ __launch_bounds__(256) void kwfbar_kernel(
    const float* __restrict__ wk, const float* __restrict__ wb,
    const float* __restrict__ feats)
{
    int q = blockIdx.x;
    __shared__ float sc[8];
    int w = threadIdx.x >> 5, lane = threadIdx.x & 31;
    const float* qr = g_q + (size_t)q * Dn;
    float s = 0.f;
    for (int d = lane; d < Dn; d += 32) s += qr[d] * wk[w*Dn + d];
    unsigned m = 0xffffffffu;
    s += __shfl_xor_sync(m, s, 16); s += __shfl_xor_sync(m, s, 8);
    s += __shfl_xor_sync(m, s, 4);  s += __shfl_xor_sync(m, s, 2);
    s += __shfl_xor_sync(m, s, 1);
    if (lane == 0) sc[w] = s + wb[w];
    __syncthreads();
    float mx = sc[0];
#pragma unroll
    for (int k = 1; k < 8; k++) mx = fmaxf(mx, sc[k]);
    float kwv[8]; float ssum = 0.f;
#pragma unroll
    for (int k = 0; k < 8; k++) { kwv[k] = expf(sc[k] - mx); ssum += kwv[k]; }
    float inv = 1.f / ssum;
    int d = threadIdx.x;
    float acc = 0.f;
#pragma unroll
    for (int k = 0; k < 8; k++) {
        int id = g_idx[q*8 + k];
        acc += kwv[k] * inv * feats[(size_t)id * Dn + d];
    }
    g_fbar[(size_t)q * Dn + d] = acc;
}

__global__ void mul_kernel() {
    int i = blockIdx.x * blockDim.x + threadIdx.x;
    if (i < Qn*Dn) g_wtmp[i] = g_q[i] * g_vbar[i];
}

// ---------------- LayerNorm: dst = LN(a [+ b]) ----------------
__global__ __launch_bounds__(256) void ln_kernel(
    float* __restrict__ dst, const float* __restrict__ a, const float* __restrict__ b)
{
    int row = blockIdx.x, d = threadIdx.x;
    float v = a[(size_t)row*Dn + d];
    if (b) v += b[(size_t)row*Dn + d];
    float mean = blockSum<256>(v) * (1.f/Dn);
    float c = v - mean;
    float var = blockSum<256>(c*c) * (1.f/Dn);
    dst[(size_t)row*Dn + d] = c * rsqrtf(var + 1e-5f);
}

__global__ void gather_kernel(const int* __restrict__ order) {
    int r = blockIdx.x;
    int src = order[r];
    g_xs[(size_t)r*Dn + threadIdx.x] = g_xn[(size_t)src*Dn + threadIdx.x];
}

__global__ void inv_kernel(const int* __restrict__ order) {
    int i = blockIdx.x * blockDim.x + threadIdx.x;
    if (i < 2*Qn) {
        int p = i >> 11, j = i & 2047;
        g_inv[p*Qn + order[i]] = j;
    }
}

// ---------------- causal depthwise conv(4) + silu ----------------
__global__ void conv_kernel(const float* __restrict__ Wc, const float* __restrict__ bc) {
    int t = blockIdx.x, b = blockIdx.y, c = threadIdx.x;
    size_t rbase = (size_t)(b*Ln + t) * NPROJn + 512 + c;
    float acc = bc[c];
#pragma unroll
    for (int j = 0; j < 4; j++) {
        int tt = t + j - 3;
        if (tt >= 0) acc += g_proj[rbase + (size_t)(tt - t) * NPROJn] * Wc[c*4 + j];
    }
    float sg = 1.f / (1.f + expf(-acc));
    g_xbc[(size_t)(b*Ln + t) * CONVn + c] = acc * sg;
}

__global__ void dt_kernel(const float* __restrict__ dtb, const float* __restrict__ Alog) {
    int i = blockIdx.x * blockDim.x + threadIdx.x;
    if (i < 2*Ln*Hn) {
        int h = i & 7, row = i >> 3;
        float x = g_proj[(size_t)row*NPROJn + 1152 + h] + dtb[h];
        float dt = (x > 20.f) ? x : log1pf(expf(x));
        float A = -expf(Alog[h]);
        g_dt[i] = dt;
        g_dAr[i] = expf(dt * A);
    }
}

// ---------------- recurrent SSM scan, smem-tiled + double-buffered ----------------
// grid 128 = b(2) x h(8) x dchunk(8), block 128 = dlocal(8) x sgroup(16, 4 s each).
// Tiles of 16 steps are staged cooperatively into smem; global latency is paid
// once per tile (hidden behind ~16 steps of compute), not once per step.
__global__ __launch_bounds__(128) void scan_kernel() {
    int bx = blockIdx.x;
    int b = bx >> 6;
    int h = (bx >> 3) & 7;
    int dch = bx & 7;
    int tid = threadIdx.x;
    int dl = tid >> 4;
    int s0 = (tid & 15) * 4;

    __shared__ float sB[2][16][64];
    __shared__ float sC[2][16][64];
    __shared__ float sx[2][16][8];
    __shared__ float sda[2][16];
    __shared__ float sdt[2][16];
    __shared__ float sacc[16][132];

    const float* xbcb = g_xbc + (size_t)b * Ln * CONVn;
    const float* dAb  = g_dAr + (size_t)b * Ln * Hn + h;
    const float* dtbp = g_dt  + (size_t)b * Ln * Hn + h;
    int xoff = h * 64 + dch * 8;

    float h0 = 0.f, h1 = 0.f, h2 = 0.f, h3 = 0.f;

    // per-thread staging registers for the next tile
    float4 rBC[4];
    float rx = 0.f, rda = 0.f, rdt = 0.f;
    int ldrow = tid >> 3, lde = tid & 7;   // x-load mapping

    // ---- load tile 0 into registers ----
#pragma unroll
    for (int r = 0; r < 4; r++) {
        int j = tid + 128 * r;          // 0..511
        int row = j >> 5, col = j & 31; // col*4 in [0,128)
        rBC[r] = *(const float4*)&xbcb[(size_t)row * CONVn + 512 + col * 4];
    }
    rx = xbcb[(size_t)ldrow * CONVn + xoff + lde];
    if (tid < 16) rda = dAb[(size_t)tid * Hn];
    else if (tid < 32) rdt = dtbp[(size_t)(tid - 16) * Hn];

    // ---- store tile 0 to smem buf 0 ----
#pragma unroll
    for (int r = 0; r < 4; r++) {
        int j = tid + 128 * r;
        int row = j >> 5, col = (j & 31) * 4;
        if (col < 64) *(float4*)&sB[0][row][col] = rBC[r];
        else          *(float4*)&sC[0][row][col - 64] = rBC[r];
    }
    sx[0][ldrow][lde] = rx;
    if (tid < 16) sda[0][tid] = rda;
    else if (tid < 32) sdt[0][tid - 16] = rdt;
    __syncthreads();

    int buf = 0;
    for (int tile = 0; tile < Ln / 16; ++tile) {
        bool more = (tile + 1) < Ln / 16;
        if (more) {
            int t0 = (tile + 1) * 16;
#pragma unroll
            for (int r = 0; r < 4; r++) {
                int j = tid + 128 * r;
                int row = j >> 5, col = j & 31;
                rBC[r] = *(const float4*)&xbcb[(size_t)(t0 + row) * CONVn + 512 + col * 4];
            }
            rx = xbcb[(size_t)(t0 + ldrow) * CONVn + xoff + lde];
            if (tid < 16) rda = dAb[(size_t)(t0 + tid) * Hn];
            else if (tid < 32) rdt = dtbp[(size_t)(t0 + tid - 16) * Hn];
        }
        // compute 16 steps from smem
#pragma unroll
        for (int tt = 0; tt < 16; ++tt) {
            float4 Bv = *(const float4*)&sB[buf][tt][s0];
            float4 Cv = *(const float4*)&sC[buf][tt][s0];
            float xv = sx[buf][tt][dl];
            float dA = sda[buf][tt], dt = sdt[buf][tt];
            float dtx = dt * xv;
            h0 = fmaf(h0, dA, dtx * Bv.x);
            h1 = fmaf(h1, dA, dtx * Bv.y);
            h2 = fmaf(h2, dA, dtx * Bv.z);
            h3 = fmaf(h3, dA, dtx * Bv.w);
            sacc[tt][tid] = h0 * Cv.x + h1 * Cv.y + h2 * Cv.z + h3 * Cv.w;
        }
        __syncthreads();
        // reduce the 16 s-groups for each (tt, d) and write y
        {
            int tt = tid >> 3, dd = tid & 7;
            float y = 0.f;
#pragma unroll
            for (int j = 0; j < 16; j++) y += sacc[tt][dd * 16 + j];
            int t = tile * 16 + tt;
            g_ys[(size_t)(b * Ln + t) * DINn + h * 64 + dch * 8 + dd] = y;
        }
        if (more) {
            int nb = buf ^ 1;
#pragma unroll
            for (int r = 0; r < 4; r++) {
                int j = tid + 128 * r;
                int row = j >> 5, col = (j & 31) * 4;
                if (col < 64) *(float4*)&sB[nb][row][col] = rBC[r];
                else          *(float4*)&sC[nb][row][col - 64] = rBC[r];
            }
            sx[nb][ldrow][lde] = rx;
            if (tid < 16) sda[nb][tid] = rda;
            else if (tid < 32) sdt[nb][tid - 16] = rdt;
        }
        __syncthreads();
        buf ^= 1;
    }
}

// ---------------- y + D*x, silu(z) gate, gated RMSNorm ----------------
__global__ __launch_bounds__(128) void gated_kernel(
    const float* __restrict__ Dl, const float* __restrict__ rmsw)
{
    int row = blockIdx.x, tid = threadIdx.x;
    float gv[4]; float ss = 0.f;
#pragma unroll
    for (int e = 0; e < 4; e++) {
        int c = e * 128 + tid;
        int h = c >> 6;
        float ys = g_ys[(size_t)row*DINn + c];
        float xh = g_xbc[(size_t)row*CONVn + c];
        float z = g_proj[(size_t)row*NPROJn + c];
        float u = ys + Dl[h] * xh;
        float g = u * (z / (1.f + expf(-z)));
        gv[e] = g;
        ss += g * g;
    }
    float tot = blockSum<128>(ss);
    float r = rsqrtf(tot * (1.f/DINn) + 1e-5f);
#pragma unroll
    for (int e = 0; e < 4; e++) {
        int c = e * 128 + tid;
        g_gated[(size_t)row*DINn + c] = gv[e] * r * rmsw[c];
    }
}

// ---------------- unsort + mean + residual + LN (updates g_x) ----------------
__global__ __launch_bounds__(256) void combine_kernel() {
    int i = blockIdx.x, d = threadIdx.x;
    int i0 = g_inv[i];
    int i1 = g_inv[Qn + i];
    float v = g_x[(size_t)i*Dn + d]
            + 0.5f * (g_mo[(size_t)i0*Dn + d] + g_mo[(size_t)(Qn + i1)*Dn + d]);
    float mean = blockSum<256>(v) * (1.f/Dn);
    float c = v - mean;
    float var = blockSum<256>(c*c) * (1.f/Dn);
    g_x[(size_t)i*Dn + d] = c * rsqrtf(var + 1e-5f);
}

// ---------------- host ----------------
extern "C" void kernel_launch(void* const* d_in, const int* in_sizes, int n_in,
                              void* d_out, int out_size) {
    const float* query  = (const float*)d_in[0];
    const float* qpos   = (const float*)d_in[1];
    const float* feats  = (const float*)d_in[2];
    const float* spc    = (const float*)d_in[3];
    const float* w_q    = (const float*)d_in[4];
    const float* w_v    = (const float*)d_in[5];
    const float* w_o    = (const float*)d_in[6];
    const float* w_k    = (const float*)d_in[7];
    const float* w_b    = (const float*)d_in[8];
    const float* Win    = (const float*)d_in[9];
    const float* Wconv  = (const float*)d_in[10];
    const float* bconv  = (const float*)d_in[11];
    const float* Alog   = (const float*)d_in[12];
    const float* Dh     = (const float*)d_in[13];
    const float* dtbias = (const float*)d_in[14];
    const float* rmsw   = (const float*)d_in[15];
    const float* Wout   = (const float*)d_in[16];
    const float* fw1    = (const float*)d_in[17];
    const float* fb1    = (const float*)d_in[18];
    const float* fw2    = (const float*)d_in[19];
    const float* fb2    = (const float*)d_in[20];
    const int*   order  = (const int*)d_in[21];
    float* out = (float*)d_out;

    void *vq, *vfbar, *vvbar, *vwtmp, *vwo, *vx, *vxn, *vxs, *vproj, *vgated, *vmo,
         *vffnh, *vffno;
    cudaGetSymbolAddress(&vq, g_q);
    cudaGetSymbolAddress(&vfbar, g_fbar);
    cudaGetSymbolAddress(&vvbar, g_vbar);
    cudaGetSymbolAddress(&vwtmp, g_wtmp);
    cudaGetSymbolAddress(&vwo, g_wo);
    cudaGetSymbolAddress(&vx, g_x);
    cudaGetSymbolAddress(&vxn, g_xn);
    cudaGetSymbolAddress(&vxs, g_xs);
    cudaGetSymbolAddress(&vproj, g_proj);
    cudaGetSymbolAddress(&vgated, g_gated);
    cudaGetSymbolAddress(&vmo, g_mo);
    cudaGetSymbolAddress(&vffnh, g_ffnh);
    cudaGetSymbolAddress(&vffno, g_ffno);
    float* p_q = (float*)vq;       float* p_fbar = (float*)vfbar;
    float* p_vbar = (float*)vvbar; float* p_wtmp = (float*)vwtmp;
    float* p_wo = (float*)vwo;     float* p_x = (float*)vx;
    float* p_xn = (float*)vxn;     float* p_xs = (float*)vxs;
    float* p_proj = (float*)vproj; float* p_gated = (float*)vgated;
    float* p_mo = (float*)vmo;     float* p_ffnh = (float*)vffnh;
    float* p_ffno = (float*)vffno;

    dim3 gb(16, 16);

    // --- stage 1: KNN + aggregation ---
    pack_sp_kernel<<<Nn/256, 256>>>(spc);
    knn_kernel<<<Qn/16, 256>>>(qpos);
    gemm_kernel<<<dim3(Dn/64, Qn/64), gb>>>(query, w_q, nullptr, p_q, Qn, Dn, Dn, 0);
    kwfbar_kernel<<<Qn, 256>>>(w_k, w_b, feats);
    gemm_kernel<<<dim3(Dn/64, Qn/64), gb>>>(p_fbar, w_v, nullptr, p_vbar, Qn, Dn, Dn, 0);
    mul_kernel<<<(Qn*Dn)/256, 256>>>();
    gemm_kernel<<<dim3(Dn/64, Qn/64), gb>>>(p_wtmp, w_o, nullptr, p_wo, Qn, Dn, Dn, 0);
    ln_kernel<<<Qn, 256>>>(p_x, p_wo, query);

    inv_kernel<<<(2*Qn)/256, 256>>>(order);

    // --- stage 2: two Mamba2 SSM layers ---
    for (int l = 0; l < 2; l++) {
        const float* Win_l   = Win   + (size_t)l * NPROJn * Dn;
        const float* Wconv_l = Wconv + (size_t)l * CONVn * KCn;
        const float* bconv_l = bconv + (size_t)l * CONVn;
        const float* Alog_l  = Alog  + l * Hn;
        const float* D_l     = Dh    + l * Hn;
        const float* dtb_l   = dtbias+ l * Hn;
        const float* rmsw_l  = rmsw  + l * DINn;
        const float* Wout_l  = Wout  + (size_t)l * Dn * DINn;

        ln_kernel<<<Qn, 256>>>(p_xn, p_x, nullptr);
        gather_kernel<<<2*Qn, 256>>>(order);
        gemm_kernel<<<dim3((NPROJn+63)/64, (2*Qn)/64), gb>>>(p_xs, Win_l, nullptr, p_proj,
                                                             2*Qn, NPROJn, Dn, 0);
        conv_kernel<<<dim3(Ln, 2), CONVn>>>(Wconv_l, bconv_l);
        dt_kernel<<<(2*Ln*Hn)/256, 256>>>(dtb_l, Alog_l);
        scan_kernel<<<128, 128>>>();
        gated_kernel<<<2*Qn, 128>>>(D_l, rmsw_l);
        gemm_kernel<<<dim3(Dn/64, (2*Qn)/64), gb>>>(p_gated, Wout_l, nullptr, p_mo,
                                                    2*Qn, Dn, DINn, 0);
        combine_kernel<<<Qn, 256>>>();
    }

    // --- stage 3: FFN ---
    gemm_kernel<<<dim3(HIDn/64, Qn/64), gb>>>(p_x, fw1, fb1, p_ffnh, Qn, HIDn, Dn, 1);
    gemm_kernel<<<dim3(Dn/64, Qn/64), gb>>>(p_ffnh, fw2, fb2, p_ffno, Qn, Dn, HIDn, 0);
    ln_kernel<<<Qn, 256>>>(out, p_ffno, p_x);
}

// round 17
// speedup vs baseline: 2.0599x; 1.1765x over previous
#include <cuda_runtime.h>
#include <math.h>

#define Qn 2048
#define Dn 256
#define Nn 32768
#define Hn 8
#define STn 64
#define DINn 512
#define CONVn 640
#define NPROJn 1160
#define HIDn 1024
#define KCn 4
#define Ln 2048

// ---------------- scratch (device globals) ----------------
__device__ float g_q[Qn*Dn];
__device__ float g_fbar[Qn*Dn];
__device__ float g_vbar[Qn*Dn];
__device__ float g_wtmp[Qn*Dn];
__device__ float g_wo[Qn*Dn];
__device__ float g_x[Qn*Dn];
__device__ float g_xn[Qn*Dn];
__device__ float g_xs[2*Qn*Dn];
__device__ float g_proj[2*Qn*NPROJn];
__device__ float g_xbc[2*Qn*CONVn];
__device__ float g_dt[2*Qn*Hn];
__device__ float g_dAr[2*Qn*Hn];
__device__ float g_ys[2*Qn*DINn];
__device__ float g_gated[2*Qn*DINn];
__device__ float g_mo[2*Qn*Dn];
__device__ float g_ffnh[Qn*HIDn];
__device__ float g_ffno[Qn*Dn];
__device__ float4 g_sp4[Nn];
__device__ int g_idx[Qn*8];
__device__ int g_inv[2*Qn];

// ---------------- helpers ----------------
template<int NT>
__device__ __forceinline__ float blockSum(float v) {
    __shared__ float sm[NT/32];
    unsigned m = 0xffffffffu;
    v += __shfl_xor_sync(m, v, 16);
    v += __shfl_xor_sync(m, v, 8);
    v += __shfl_xor_sync(m, v, 4);
    v += __shfl_xor_sync(m, v, 2);
    v += __shfl_xor_sync(m, v, 1);
    int w = threadIdx.x >> 5;
    if ((threadIdx.x & 31) == 0) sm[w] = v;
    __syncthreads();
    float t = sm[0];
#pragma unroll
    for (int k = 1; k < NT/32; k++) t += sm[k];
    __syncthreads();
    return t;
}

__device__ __forceinline__ unsigned f2tf32(float x) {
    unsigned r;
    asm("cvt.rna.tf32.f32 %0, %1;" : "=r"(r) : "f"(x));
    return r;
}

__device__ __forceinline__ void mma_tf32(float* c, const unsigned* a, const unsigned* b) {
    asm volatile(
        "mma.sync.aligned.m16n8k8.row.col.f32.tf32.tf32.f32 "
        "{%0,%1,%2,%3}, {%4,%5,%6,%7}, {%8,%9}, {%0,%1,%2,%3};"
        : "+f"(c[0]), "+f"(c[1]), "+f"(c[2]), "+f"(c[3])
        : "r"(a[0]), "r"(a[1]), "r"(a[2]), "r"(a[3]), "r"(b[0]), "r"(b[1]));
}

// ============ tf32 tensor-core GEMM: C = act(A[M,K] @ W[N,K]^T + bias) ============
// BM=128, BN=64, BK=16 double-buffered. 256 threads = 8 warps (4 m x 2 n),
// warp tile 32x32 = 2 mtiles x 4 ntiles of m16n8k8.
// Requires M%128==0, K%16==0, N%8==0.
__global__ __launch_bounds__(256) void gemm_tc(
    const float* __restrict__ A, const float* __restrict__ W,
    const float* __restrict__ bias, float* __restrict__ C,
    int M, int N, int K, int act)
{
    __shared__ unsigned As[2][16][136];   // [k][m], stride 136 -> bank 8*t4+g distinct
    __shared__ unsigned Ws[2][16][72];    // [k][n], stride 72  -> bank 8*t4+g distinct

    int tid = threadIdx.x;
    int wid = tid >> 5, lane = tid & 31;
    int g = lane >> 2, t4 = lane & 3;
    int m0 = blockIdx.y * 128;
    int n0 = blockIdx.x * 64;
    int wm = (wid >> 1) * 32;
    int wn = (wid & 1) * 32;

    int arow = tid >> 2;            // 0..63 (and +64)
    int akc  = (tid & 3) * 4;       // 0,4,8,12
    int wrow = tid >> 2;            // 0..63
    bool wok = (n0 + wrow) < N;

    float acc[2][4][4];
#pragma unroll
    for (int mt = 0; mt < 2; mt++)
#pragma unroll
        for (int nt = 0; nt < 4; nt++)
#pragma unroll
            for (int e = 0; e < 4; e++) acc[mt][nt][e] = 0.f;

    const float* A0 = A + (size_t)(m0 + arow) * K + akc;
    const float* A1 = A + (size_t)(m0 + arow + 64) * K + akc;
    const float* W0 = W + (size_t)(n0 + wrow) * K + akc;

    float4 av0 = *(const float4*)A0;
    float4 av1 = *(const float4*)A1;
    float4 wv  = wok ? *(const float4*)W0 : make_float4(0.f,0.f,0.f,0.f);

    As[0][akc+0][arow] = f2tf32(av0.x); As[0][akc+1][arow] = f2tf32(av0.y);
    As[0][akc+2][arow] = f2tf32(av0.z); As[0][akc+3][arow] = f2tf32(av0.w);
    As[0][akc+0][arow+64] = f2tf32(av1.x); As[0][akc+1][arow+64] = f2tf32(av1.y);
    As[0][akc+2][arow+64] = f2tf32(av1.z); As[0][akc+3][arow+64] = f2tf32(av1.w);
    Ws[0][akc+0][wrow] = f2tf32(wv.x); Ws[0][akc+1][wrow] = f2tf32(wv.y);
    Ws[0][akc+2][wrow] = f2tf32(wv.z); Ws[0][akc+3][wrow] = f2tf32(wv.w);
    __syncthreads();

    int buf = 0;
    int ntiles = K / 16;
    for (int kt = 0; kt < ntiles; kt++) {
        bool more = (kt + 1) < ntiles;
        if (more) {
            int k = (kt + 1) * 16;
            av0 = *(const float4*)(A0 + k);
            av1 = *(const float4*)(A1 + k);
            wv  = wok ? *(const float4*)(W0 + k) : make_float4(0.f,0.f,0.f,0.f);
        }
#pragma unroll
        for (int kk = 0; kk < 2; kk++) {
            int k0 = kk * 8;
            unsigned a[2][4], bf[4][2];
#pragma unroll
            for (int mt = 0; mt < 2; mt++) {
                int mb = wm + mt * 16 + g;
                a[mt][0] = As[buf][k0 + t4][mb];
                a[mt][1] = As[buf][k0 + t4][mb + 8];
                a[mt][2] = As[buf][k0 + t4 + 4][mb];
                a[mt][3] = As[buf][k0 + t4 + 4][mb + 8];
            }
#pragma unroll
            for (int nt = 0; nt < 4; nt++) {
                int nb = wn + nt * 8 + g;
                bf[nt][0] = Ws[buf][k0 + t4][nb];
                bf[nt][1] = Ws[buf][k0 + t4 + 4][nb];
            }
#pragma unroll
            for (int mt = 0; mt < 2; mt++)
#pragma unroll
                for (int nt = 0; nt < 4; nt++)
                    mma_tf32(acc[mt][nt], a[mt], bf[nt]);
        }
        if (more) {
            int nb = buf ^ 1;
            As[nb][akc+0][arow] = f2tf32(av0.x); As[nb][akc+1][arow] = f2tf32(av0.y);
            As[nb][akc+2][arow] = f2tf32(av0.z); As[nb][akc+3][arow] = f2tf32(av0.w);
            As[nb][akc+0][arow+64] = f2tf32(av1.x); As[nb][akc+1][arow+64] = f2tf32(av1.y);
            As[nb][akc+2][arow+64] = f2tf32(av1.z); As[nb][akc+3][arow+64] = f2tf32(av1.w);
            Ws[nb][akc+0][wrow] = f2tf32(wv.x); Ws[nb][akc+1][wrow] = f2tf32(wv.y);
            Ws[nb][akc+2][wrow] = f2tf32(wv.z); Ws[nb][akc+3][wrow] = f2tf32(wv.w);
        }
        __syncthreads();
        buf ^= 1;
    }

    // epilogue
#pragma unroll
    for (int mt = 0; mt < 2; mt++) {
        int mrow = m0 + wm + mt * 16 + g;
#pragma unroll
        for (int nt = 0; nt < 4; nt++) {
            int ntile0 = n0 + wn + nt * 8;
            if (ntile0 >= N) continue;
            int ncol = ntile0 + 2 * t4;
            float c0 = acc[mt][nt][0], c1 = acc[mt][nt][1];
            float c2 = acc[mt][nt][2], c3 = acc[mt][nt][3];
            if (bias) {
                float b0 = bias[ncol], b1 = bias[ncol + 1];
                c0 += b0; c1 += b1; c2 += b0; c3 += b1;
            }
            if (act == 1) {
                c0 = 0.5f * c0 * (1.f + erff(c0 * 0.7071067811865475f));
                c1 = 0.5f * c1 * (1.f + erff(c1 * 0.7071067811865475f));
                c2 = 0.5f * c2 * (1.f + erff(c2 * 0.7071067811865475f));
                c3 = 0.5f * c3 * (1.f + erff(c3 * 0.7071067811865475f));
            }
            *(float2*)&C[(size_t)mrow * N + ncol] = make_float2(c0, c1);
            *(float2*)&C[(size_t)(mrow + 8) * N + ncol] = make_float2(c2, c3);
        }
    }
}

// ---------------- pack sp coords ----------------
__global__ void pack_sp_kernel(const float* __restrict__ sp) {
    int i = blockIdx.x * blockDim.x + threadIdx.x;
    if (i < Nn) {
        float x = sp[3*i], y = sp[3*i+1], z = sp[3*i+2];
        g_sp4[i] = make_float4(x, y, z, x*x + y*y + z*z);
    }
}

// ---------------- KNN ----------------
__device__ __forceinline__ bool knn_less(float da, int ia, float db, int ib) {
    return (da < db) || (da == db && ia < ib);
}

__global__ __launch_bounds__(256) void knn_kernel(const float* __restrict__ qpos) {
    __shared__ float4 tile[2048];
    int tid = threadIdx.x;
    int ql = tid & 15;
    int lg = tid >> 4;
    int q = blockIdx.x * 16 + ql;
    float qx = qpos[3*q], qy = qpos[3*q+1], qz = qpos[3*q+2];

    float bd[8]; int bi[8];
#pragma unroll
    for (int j = 0; j < 8; j++) { bd[j] = 3.4e38f; bi[j] = 0x7fffffff; }

    for (int tb = 0; tb < Nn; tb += 2048) {
        __syncthreads();
        for (int i = tid; i < 2048; i += 256) tile[i] = g_sp4[tb + i];
        __syncthreads();
        for (int i = lg; i < 2048; i += 16) {
            float4 s = tile[i];
            float d = s.w - 2.f * (qx*s.x + qy*s.y + qz*s.z);
            int n = tb + i;
            if (knn_less(d, n, bd[7], bi[7])) {
                float cd = d; int ci = n;
#pragma unroll
                for (int p = 0; p < 8; p++) {
                    if (knn_less(cd, ci, bd[p], bi[p])) {
                        float tf = bd[p]; bd[p] = cd; cd = tf;
                        int ti = bi[p]; bi[p] = ci; ci = ti;
                    }
                }
            }
        }
    }
    __syncthreads();
    float* sd = (float*)tile;
    int* si = (int*)(sd + 2048);
#pragma unroll
    for (int j = 0; j < 8; j++) { sd[tid*8+j] = bd[j]; si[tid*8+j] = bi[j]; }
    __syncthreads();
    for (int st = 8; st >= 1; st >>= 1) {
        if (lg < st) {
            int op = tid + st * 16;
#pragma unroll
            for (int j = 0; j < 8; j++) {
                float cd = sd[op*8+j]; int ci = si[op*8+j];
                if (knn_less(cd, ci, bd[7], bi[7])) {
#pragma unroll
                    for (int p = 0; p < 8; p++) {
                        if (knn_less(cd, ci, bd[p], bi[p])) {
                            float tf = bd[p]; bd[p] = cd; cd = tf;
                            int ti = bi[p]; bi[p] = ci; ci = ti;
                        }
                    }
                }
            }
#pragma unroll
            for (int j = 0; j < 8; j++) { sd[tid*8+j] = bd[j]; si[tid*8+j] = bi[j]; }
        }
        __syncthreads();
    }
    if (lg == 0) {
#pragma unroll
        for (int j = 0; j < 8; j++) g_idx[q*8+j] = bi[j];
    }
}

// ---------------- kw softmax + weighted feature mix ----------------
__global__ __launch_bounds__(256) void kwfbar_kernel(
    const float* __restrict__ wk, const float* __restrict__ wb,
    const float* __restrict__ feats)
{
    int q = blockIdx.x;
    __shared__ float sc[8];
    int w = threadIdx.x >> 5, lane = threadIdx.x & 31;
    const float* qr = g_q + (size_t)q * Dn;
    float s = 0.f;
    for (int d = lane; d < Dn; d += 32) s += qr[d] * wk[w*Dn + d];
    unsigned m = 0xffffffffu;
    s += __shfl_xor_sync(m, s, 16); s += __shfl_xor_sync(m, s, 8);
    s += __shfl_xor_sync(m, s, 4);  s += __shfl_xor_sync(m, s, 2);
    s += __shfl_xor_sync(m, s, 1);
    if (lane == 0) sc[w] = s + wb[w];
    __syncthreads();
    float mx = sc[0];
#pragma unroll
    for (int k = 1; k < 8; k++) mx = fmaxf(mx, sc[k]);
    float kwv[8]; float ssum = 0.f;
#pragma unroll
    for (int k = 0; k < 8; k++) { kwv[k] = expf(sc[k] - mx); ssum += kwv[k]; }
    float inv = 1.f / ssum;
    int d = threadIdx.x;
    float acc = 0.f;
#pragma unroll
    for (int k = 0; k < 8; k++) {
        int id = g_idx[q*8 + k];
        acc += kwv[k] * inv * feats[(size_t)id * Dn + d];
    }
    g_fbar[(size_t)q * Dn + d] = acc;
}

__global__ void mul_kernel() {
    int i = blockIdx.x * blockDim.x + threadIdx.x;
    if (i < Qn*Dn) g_wtmp[i] = g_q[i] * g_vbar[i];
}

// ---------------- LayerNorm: dst = LN(a [+ b]) ----------------
__global__ __launch_bounds__(256) void ln_kernel(
    float* __restrict__ dst, const float* __restrict__ a, const float* __restrict__ b)
{
    int row = blockIdx.x, d = threadIdx.x;
    float v = a[(size_t)row*Dn + d];
    if (b) v += b[(size_t)row*Dn + d];
    float mean = blockSum<256>(v) * (1.f/Dn);
    float c = v - mean;
    float var = blockSum<256>(c*c) * (1.f/Dn);
    dst[(size_t)row*Dn + d] = c * rsqrtf(var + 1e-5f);
}

__global__ void gather_kernel(const int* __restrict__ order) {
    int r = blockIdx.x;
    int src = order[r];
    g_xs[(size_t)r*Dn + threadIdx.x] = g_xn[(size_t)src*Dn + threadIdx.x];
}

__global__ void inv_kernel(const int* __restrict__ order) {
    int i = blockIdx.x * blockDim.x + threadIdx.x;
    if (i < 2*Qn) {
        int p = i >> 11, j = i & 2047;
        g_inv[p*Qn + order[i]] = j;
    }
}

// ---------------- causal depthwise conv(4) + silu ----------------
__global__ void conv_kernel(const float* __restrict__ Wc, const float* __restrict__ bc) {
    int t = blockIdx.x, b = blockIdx.y, c = threadIdx.x;
    size_t rbase = (size_t)(b*Ln + t) * NPROJn + 512 + c;
    float acc = bc[c];
#pragma unroll
    for (int j = 0; j < 4; j++) {
        int tt = t + j - 3;
        if (tt >= 0) acc += g_proj[rbase + (size_t)(tt - t) * NPROJn] * Wc[c*4 + j];
    }
    float sg = 1.f / (1.f + expf(-acc));
    g_xbc[(size_t)(b*Ln + t) * CONVn + c] = acc * sg;
}

__global__ void dt_kernel(const float* __restrict__ dtb, const float* __restrict__ Alog) {
    int i = blockIdx.x * blockDim.x + threadIdx.x;
    if (i < 2*Ln*Hn) {
        int h = i & 7, row = i >> 3;
        float x = g_proj[(size_t)row*NPROJn + 1152 + h] + dtb[h];
        float dt = (x > 20.f) ? x : log1pf(expf(x));
        float A = -expf(Alog[h]);
        g_dt[i] = dt;
        g_dAr[i] = expf(dt * A);
    }
}

// ---------------- recurrent SSM scan, smem-tiled + double-buffered ----------------
__global__ __launch_bounds__(128) void scan_kernel() {
    int bx = blockIdx.x;
    int b = bx >> 6;
    int h = (bx >> 3) & 7;
    int dch = bx & 7;
    int tid = threadIdx.x;
    int dl = tid >> 4;
    int s0 = (tid & 15) * 4;

    __shared__ float sB[2][16][64];
    __shared__ float sC[2][16][64];
    __shared__ float sx[2][16][8];
    __shared__ float sda[2][16];
    __shared__ float sdt[2][16];
    __shared__ float sacc[16][132];

    const float* xbcb = g_xbc + (size_t)b * Ln * CONVn;
    const float* dAb  = g_dAr + (size_t)b * Ln * Hn + h;
    const float* dtbp = g_dt  + (size_t)b * Ln * Hn + h;
    int xoff = h * 64 + dch * 8;

    float h0 = 0.f, h1 = 0.f, h2 = 0.f, h3 = 0.f;

    float4 rBC[4];
    float rx = 0.f, rda = 0.f, rdt = 0.f;
    int ldrow = tid >> 3, lde = tid & 7;

#pragma unroll
    for (int r = 0; r < 4; r++) {
        int j = tid + 128 * r;
        int row = j >> 5, col = j & 31;
        rBC[r] = *(const float4*)&xbcb[(size_t)row * CONVn + 512 + col * 4];
    }
    rx = xbcb[(size_t)ldrow * CONVn + xoff + lde];
    if (tid < 16) rda = dAb[(size_t)tid * Hn];
    else if (tid < 32) rdt = dtbp[(size_t)(tid - 16) * Hn];

#pragma unroll
    for (int r = 0; r < 4; r++) {
        int j = tid + 128 * r;
        int row = j >> 5, col = (j & 31) * 4;
        if (col < 64) *(float4*)&sB[0][row][col] = rBC[r];
        else          *(float4*)&sC[0][row][col - 64] = rBC[r];
    }
    sx[0][ldrow][lde] = rx;
    if (tid < 16) sda[0][tid] = rda;
    else if (tid < 32) sdt[0][tid - 16] = rdt;
    __syncthreads();

    int buf = 0;
    for (int tile = 0; tile < Ln / 16; ++tile) {
        bool more = (tile + 1) < Ln / 16;
        if (more) {
            int t0 = (tile + 1) * 16;
#pragma unroll
            for (int r = 0; r < 4; r++) {
                int j = tid + 128 * r;
                int row = j >> 5, col = j & 31;
                rBC[r] = *(const float4*)&xbcb[(size_t)(t0 + row) * CONVn + 512 + col * 4];
            }
            rx = xbcb[(size_t)(t0 + ldrow) * CONVn + xoff + lde];
            if (tid < 16) rda = dAb[(size_t)(t0 + tid) * Hn];
            else if (tid < 32) rdt = dtbp[(size_t)(t0 + tid - 16) * Hn];
        }
#pragma unroll
        for (int tt = 0; tt < 16; ++tt) {
            float4 Bv = *(const float4*)&sB[buf][tt][s0];
            float4 Cv = *(const float4*)&sC[buf][tt][s0];
            float xv = sx[buf][tt][dl];
            float dA = sda[buf][tt], dt = sdt[buf][tt];
            float dtx = dt * xv;
            h0 = fmaf(h0, dA, dtx * Bv.x);
            h1 = fmaf(h1, dA, dtx * Bv.y);
            h2 = fmaf(h2, dA, dtx * Bv.z);
            h3 = fmaf(h3, dA, dtx * Bv.w);
            sacc[tt][tid] = h0 * Cv.x + h1 * Cv.y + h2 * Cv.z + h3 * Cv.w;
        }
        __syncthreads();
        {
            int tt = tid >> 3, dd = tid & 7;
            float y = 0.f;
#pragma unroll
            for (int j = 0; j < 16; j++) y += sacc[tt][dd * 16 + j];
            int t = tile * 16 + tt;
            g_ys[(size_t)(b * Ln + t) * DINn + h * 64 + dch * 8 + dd] = y;
        }
        if (more) {
            int nb = buf ^ 1;
#pragma unroll
            for (int r = 0; r < 4; r++) {
                int j = tid + 128 * r;
                int row = j >> 5, col = (j & 31) * 4;
                if (col < 64) *(float4*)&sB[nb][row][col] = rBC[r];
                else          *(float4*)&sC[nb][row][col - 64] = rBC[r];
            }
            sx[nb][ldrow][lde] = rx;
            if (tid < 16) sda[nb][tid] = rda;
            else if (tid < 32) sdt[nb][tid - 16] = rdt;
        }
        __syncthreads();
        buf ^= 1;
    }
}

// ---------------- y + D*x, silu(z) gate, gated RMSNorm ----------------
__global__ __launch_bounds__(128) void gated_kernel(
    const float* __restrict__ Dl, const float* __restrict__ rmsw)
{
    int row = blockIdx.x, tid = threadIdx.x;
    float gv[4]; float ss = 0.f;
#pragma unroll
    for (int e = 0; e < 4; e++) {
        int c = e * 128 + tid;
        int h = c >> 6;
        float ys = g_ys[(size_t)row*DINn + c];
        float xh = g_xbc[(size_t)row*CONVn + c];
        float z = g_proj[(size_t)row*NPROJn + c];
        float u = ys + Dl[h] * xh;
        float g = u * (z / (1.f + expf(-z)));
        gv[e] = g;
        ss += g * g;
    }
    float tot = blockSum<128>(ss);
    float r = rsqrtf(tot * (1.f/DINn) + 1e-5f);
#pragma unroll
    for (int e = 0; e < 4; e++) {
        int c = e * 128 + tid;
        g_gated[(size_t)row*DINn + c] = gv[e] * r * rmsw[c];
    }
}

// ---------------- unsort + mean + residual + LN (updates g_x) ----------------
__global__ __launch_bounds__(256) void combine_kernel() {
    int i = blockIdx.x, d = threadIdx.x;
    int i0 = g_inv[i];
    int i1 = g_inv[Qn + i];
    float v = g_x[(size_t)i*Dn + d]
            + 0.5f * (g_mo[(size_t)i0*Dn + d] + g_mo[(size_t)(Qn + i1)*Dn + d]);
    float mean = blockSum<256>(v) * (1.f/Dn);
    float c = v - mean;
    float var = blockSum<256>(c*c) * (1.f/Dn);
    g_x[(size_t)i*Dn + d] = c * rsqrtf(var + 1e-5f);
}

// ---------------- host ----------------
extern "C" void kernel_launch(void* const* d_in, const int* in_sizes, int n_in,
                              void* d_out, int out_size) {
    const float* query  = (const float*)d_in[0];
    const float* qpos   = (const float*)d_in[1];
    const float* feats  = (const float*)d_in[2];
    const float* spc    = (const float*)d_in[3];
    const float* w_q    = (const float*)d_in[4];
    const float* w_v    = (const float*)d_in[5];
    const float* w_o    = (const float*)d_in[6];
    const float* w_k    = (const float*)d_in[7];
    const float* w_b    = (const float*)d_in[8];
    const float* Win    = (const float*)d_in[9];
    const float* Wconv  = (const float*)d_in[10];
    const float* bconv  = (const float*)d_in[11];
    const float* Alog   = (const float*)d_in[12];
    const float* Dh     = (const float*)d_in[13];
    const float* dtbias = (const float*)d_in[14];
    const float* rmsw   = (const float*)d_in[15];
    const float* Wout   = (const float*)d_in[16];
    const float* fw1    = (const float*)d_in[17];
    const float* fb1    = (const float*)d_in[18];
    const float* fw2    = (const float*)d_in[19];
    const float* fb2    = (const float*)d_in[20];
    const int*   order  = (const int*)d_in[21];
    float* out = (float*)d_out;

    void *vq, *vfbar, *vvbar, *vwtmp, *vwo, *vx, *vxn, *vxs, *vproj, *vgated, *vmo,
         *vffnh, *vffno;
    cudaGetSymbolAddress(&vq, g_q);
    cudaGetSymbolAddress(&vfbar, g_fbar);
    cudaGetSymbolAddress(&vvbar, g_vbar);
    cudaGetSymbolAddress(&vwtmp, g_wtmp);
    cudaGetSymbolAddress(&vwo, g_wo);
    cudaGetSymbolAddress(&vx, g_x);
    cudaGetSymbolAddress(&vxn, g_xn);
    cudaGetSymbolAddress(&vxs, g_xs);
    cudaGetSymbolAddress(&vproj, g_proj);
    cudaGetSymbolAddress(&vgated, g_gated);
    cudaGetSymbolAddress(&vmo, g_mo);
    cudaGetSymbolAddress(&vffnh, g_ffnh);
    cudaGetSymbolAddress(&vffno, g_ffno);
    float* p_q = (float*)vq;       float* p_fbar = (float*)vfbar;
    float* p_vbar = (float*)vvbar; float* p_wtmp = (float*)vwtmp;
    float* p_wo = (float*)vwo;     float* p_x = (float*)vx;
    float* p_xn = (float*)vxn;     float* p_xs = (float*)vxs;
    float* p_proj = (float*)vproj; float* p_gated = (float*)vgated;
    float* p_mo = (float*)vmo;     float* p_ffnh = (float*)vffnh;
    float* p_ffno = (float*)vffno;

    // --- stage 1: KNN + aggregation ---
    pack_sp_kernel<<<Nn/256, 256>>>(spc);
    knn_kernel<<<Qn/16, 256>>>(qpos);
    gemm_tc<<<dim3(Dn/64, Qn/128), 256>>>(query, w_q, nullptr, p_q, Qn, Dn, Dn, 0);
    kwfbar_kernel<<<Qn, 256>>>(w_k, w_b, feats);
    gemm_tc<<<dim3(Dn/64, Qn/128), 256>>>(p_fbar, w_v, nullptr, p_vbar, Qn, Dn, Dn, 0);
    mul_kernel<<<(Qn*Dn)/256, 256>>>();
    gemm_tc<<<dim3(Dn/64, Qn/128), 256>>>(p_wtmp, w_o, nullptr, p_wo, Qn, Dn, Dn, 0);
    ln_kernel<<<Qn, 256>>>(p_x, p_wo, query);

    inv_kernel<<<(2*Qn)/256, 256>>>(order);

    // --- stage 2: two Mamba2 SSM layers ---
    for (int l = 0; l < 2; l++) {
        const float* Win_l   = Win   + (size_t)l * NPROJn * Dn;
        const float* Wconv_l = Wconv + (size_t)l * CONVn * KCn;
        const float* bconv_l = bconv + (size_t)l * CONVn;
        const float* Alog_l  = Alog  + l * Hn;
        const float* D_l     = Dh    + l * Hn;
        const float* dtb_l   = dtbias+ l * Hn;
        const float* rmsw_l  = rmsw  + l * DINn;
        const float* Wout_l  = Wout  + (size_t)l * Dn * DINn;

        ln_kernel<<<Qn, 256>>>(p_xn, p_x, nullptr);
        gather_kernel<<<2*Qn, 256>>>(order);
        gemm_tc<<<dim3((NPROJn + 63)/64, (2*Qn)/128), 256>>>(
            p_xs, Win_l, nullptr, p_proj, 2*Qn, NPROJn, Dn, 0);
        conv_kernel<<<dim3(Ln, 2), CONVn>>>(Wconv_l, bconv_l);
        dt_kernel<<<(2*Ln*Hn)/256, 256>>>(dtb_l, Alog_l);
        scan_kernel<<<128, 128>>>();
        gated_kernel<<<2*Qn, 128>>>(D_l, rmsw_l);
        gemm_tc<<<dim3(Dn/64, (2*Qn)/128), 256>>>(
            p_gated, Wout_l, nullptr, p_mo, 2*Qn, Dn, DINn, 0);
        combine_kernel<<<Qn, 256>>>();
    }

    // --- stage 3: FFN ---
    gemm_tc<<<dim3(HIDn/64, Qn/128), 256>>>(p_x, fw1, fb1, p_ffnh, Qn, HIDn, Dn, 1);
    gemm_tc<<<dim3(Dn/64, Qn/128), 256>>>(p_ffnh, fw2, fb2, p_ffno, Qn, Dn, HIDn, 0);
    ln_kernel<<<Qn, 256>>>(out, p_ffno, p_x);
}